// round 5
// baseline (speedup 1.0000x reference)
#include <cuda_runtime.h>
#include <cuda_bf16.h>
#include <cstdint>

// ---------------------------------------------------------------------------
// Problem constants
// ---------------------------------------------------------------------------
#define B_DIM 4
#define N_DIM 2048
#define K_DIM 4096
#define M_DIM 4096
#define NNZ_PER_ROW 409
#define NNZ_TOT (M_DIM * NNZ_PER_ROW)
#define NTOT (B_DIM * N_DIM)            // 8192 GEMM columns

// GEMM tiling
#define TILE_M 128
#define TILE_N 128
#define TILE_K 32
#define NCHUNK (K_DIM / TILE_K)         // 128
#define STAGES 3

// smem layout: per stage 4 operand tiles (Ah, Al, Bh, Bl), each 128 rows of
// 16 kpair-words + 4 pad words (stride 20 -> conflict-free for (g,t) pattern)
#define ROW_W 20
#define OP_WORDS (128 * ROW_W)          // 2560
#define STAGE_WORDS (4 * OP_WORDS)      // 10240 words = 40 KB
#define SMEM_BYTES (STAGES * STAGE_WORDS * 4)   // 120 KB

// ---------------------------------------------------------------------------
// Device scratch (sanctioned no-alloc mechanism)
// ---------------------------------------------------------------------------
__device__ float    g_W  [(size_t)M_DIM * K_DIM];          // 64 MB dense fp32 W
__device__ uint32_t g_Whi[(size_t)M_DIM * K_DIM / 2];      // bf16 pairs, 32 MB
__device__ uint32_t g_Wlo[(size_t)M_DIM * K_DIM / 2];
__device__ uint32_t g_Xhi[(size_t)NTOT * K_DIM / 2];       // 64 MB
__device__ uint32_t g_Xlo[(size_t)NTOT * K_DIM / 2];

// ---------------------------------------------------------------------------
// Helpers
// ---------------------------------------------------------------------------
__device__ __forceinline__ uint32_t smem_to_u32(const void* p) {
    uint32_t a;
    asm("{ .reg .u64 t; cvta.to.shared.u64 t, %1; cvt.u32.u64 %0, t; }"
        : "=r"(a) : "l"(p));
    return a;
}

// pack two floats into bf16x2 (low half = first arg)
__device__ __forceinline__ uint32_t pack_bf16x2(float lo, float hi) {
    uint32_t r;
    asm("cvt.rn.bf16x2.f32 %0, %2, %1;" : "=r"(r) : "f"(lo), "f"(hi));
    return r;
}

// split a float4 (4 consecutive k) into hi/lo bf16 pair words
__device__ __forceinline__ void split4(float4 v, uint2& h, uint2& l) {
    h.x = pack_bf16x2(v.x, v.y);
    h.y = pack_bf16x2(v.z, v.w);
    float rx = v.x - __uint_as_float(h.x << 16);
    float ry = v.y - __uint_as_float(h.x & 0xFFFF0000u);
    float rz = v.z - __uint_as_float(h.y << 16);
    float rw = v.w - __uint_as_float(h.y & 0xFFFF0000u);
    l.x = pack_bf16x2(rx, ry);
    l.y = pack_bf16x2(rz, rw);
}

__device__ __forceinline__ void cp_async16(uint32_t dst, const void* src) {
    asm volatile("cp.async.cg.shared.global [%0], [%1], 16;"
                 :: "r"(dst), "l"(src) : "memory");
}
__device__ __forceinline__ void cp_commit() {
    asm volatile("cp.async.commit_group;" ::: "memory");
}
template <int N>
__device__ __forceinline__ void cp_wait() {
    asm volatile("cp.async.wait_group %0;" :: "n"(N) : "memory");
}

// mma.sync m16n8k16 bf16 (baseline PTX, works on compute_103)
__device__ __forceinline__ void mma16816(float* c, const uint32_t* a, const uint32_t* b) {
    asm volatile(
        "mma.sync.aligned.m16n8k16.row.col.f32.bf16.bf16.f32 "
        "{%0,%1,%2,%3}, {%4,%5,%6,%7}, {%8,%9}, {%0,%1,%2,%3};"
        : "+f"(c[0]), "+f"(c[1]), "+f"(c[2]), "+f"(c[3])
        : "r"(a[0]), "r"(a[1]), "r"(a[2]), "r"(a[3]), "r"(b[0]), "r"(b[1]));
}

// ---------------------------------------------------------------------------
// Kernel 1: zero dense W
// ---------------------------------------------------------------------------
__global__ void zero_w() {
    size_t i = (size_t)blockIdx.x * blockDim.x + threadIdx.x;
    reinterpret_cast<float4*>(g_W)[i] = make_float4(0.f, 0.f, 0.f, 0.f);
}

// ---------------------------------------------------------------------------
// Kernel 2: scatter CSR -> dense fp32 W (duplicate cols sum via atomicAdd)
// ---------------------------------------------------------------------------
__global__ void scatter_w(const float* __restrict__ vals,
                          const int* __restrict__ roff,
                          const int* __restrict__ cidx, int nnz) {
    int i = blockIdx.x * blockDim.x + threadIdx.x;
    if (i >= nnz) return;
    int lo = 0, hi = M_DIM;
    while (lo + 1 < hi) {
        int mid = (lo + hi) >> 1;
        if (roff[mid] <= i) lo = mid; else hi = mid;
    }
    atomicAdd(g_W + (size_t)lo * K_DIM + cidx[i], vals[i]);
}

// ---------------------------------------------------------------------------
// Kernel 3/4: fp32 -> bf16 hi/lo split conversion
// ---------------------------------------------------------------------------
__global__ void conv_split(const float* __restrict__ src,
                           uint32_t* __restrict__ dhi,
                           uint32_t* __restrict__ dlo) {
    size_t i = (size_t)blockIdx.x * blockDim.x + threadIdx.x;
    float4 v = reinterpret_cast<const float4*>(src)[i];
    uint2 h, l;
    split4(v, h, l);
    reinterpret_cast<uint2*>(dhi)[i] = h;
    reinterpret_cast<uint2*>(dlo)[i] = l;
}

// ---------------------------------------------------------------------------
// Kernel 5: bf16x3 GEMM via mma.sync.
//   D[m, j] = sum_k W[m,k] * X[j,k]   (A row-major, B col-major: both K-contig)
//   CTA 128x128, 8 warps (4x2), warp 32x64, TILE_K=32, 3-stage cp.async.
// ---------------------------------------------------------------------------
__global__ void __launch_bounds__(256, 1) spmm_gemm(float* __restrict__ out) {
    extern __shared__ uint32_t sm[];
    const uint32_t smem_base = smem_to_u32(sm);

    const int tid  = threadIdx.x;
    const int wid  = tid >> 5;
    const int lane = tid & 31;
    const int g    = lane >> 2;     // group-of-4 id
    const int t    = lane & 3;

    const int m0 = blockIdx.y * TILE_M;
    const int j0 = blockIdx.x * TILE_N;
    const int warp_m = (wid >> 1) * 32;
    const int warp_n = (wid & 1) * 64;

    float acc[2][8][4];
#pragma unroll
    for (int mt = 0; mt < 2; ++mt)
#pragma unroll
        for (int nt = 0; nt < 8; ++nt)
#pragma unroll
            for (int q = 0; q < 4; ++q) acc[mt][nt][q] = 0.f;

    // ---- stage loader: 2048 x 16B chunks, 8 per thread ----
    auto issue_stage = [&](int stage, int chunk) {
        const int k0 = chunk * TILE_K;
        const uint32_t sbase = smem_base + (uint32_t)stage * STAGE_WORDS * 4;
#pragma unroll
        for (int i = 0; i < 8; ++i) {
            const int cid = tid + i * 256;
            const int seg = cid & 3;
            const int row = (cid >> 2) & 127;
            const int op  = cid >> 9;            // 0=Ah 1=Al 2=Bh 3=Bl
            const int grow = (op < 2) ? (m0 + row) : (j0 + row);
            const size_t pidx = ((size_t)grow * K_DIM + k0 + seg * 8) >> 1;
            const uint32_t* src =
                (op == 0) ? (g_Whi + pidx) :
                (op == 1) ? (g_Wlo + pidx) :
                (op == 2) ? (g_Xhi + pidx) : (g_Xlo + pidx);
            const uint32_t dst = sbase + (uint32_t)(op * OP_WORDS + row * ROW_W + seg * 4) * 4;
            cp_async16(dst, src);
        }
    };

    // prologue
    issue_stage(0, 0); cp_commit();
    issue_stage(1, 1); cp_commit();

    for (int c = 0; c < NCHUNK; ++c) {
        cp_wait<1>();
        __syncthreads();

        const uint32_t* Ah = sm + (c % STAGES) * STAGE_WORDS;
        const uint32_t* Al = Ah + OP_WORDS;
        const uint32_t* Bh = Ah + 2 * OP_WORDS;
        const uint32_t* Bl = Ah + 3 * OP_WORDS;

#pragma unroll
        for (int ks = 0; ks < 2; ++ks) {
            const int kb = ks * 8;
            uint32_t ah[2][4], al[2][4], bh[8][2], bl[8][2];
#pragma unroll
            for (int mt = 0; mt < 2; ++mt) {
                const int rb = warp_m + mt * 16;
                ah[mt][0] = Ah[(rb + g) * ROW_W + kb + t];
                ah[mt][1] = Ah[(rb + g + 8) * ROW_W + kb + t];
                ah[mt][2] = Ah[(rb + g) * ROW_W + kb + t + 4];
                ah[mt][3] = Ah[(rb + g + 8) * ROW_W + kb + t + 4];
                al[mt][0] = Al[(rb + g) * ROW_W + kb + t];
                al[mt][1] = Al[(rb + g + 8) * ROW_W + kb + t];
                al[mt][2] = Al[(rb + g) * ROW_W + kb + t + 4];
                al[mt][3] = Al[(rb + g + 8) * ROW_W + kb + t + 4];
            }
#pragma unroll
            for (int nt = 0; nt < 8; ++nt) {
                const int cb = warp_n + nt * 8 + g;
                bh[nt][0] = Bh[cb * ROW_W + kb + t];
                bh[nt][1] = Bh[cb * ROW_W + kb + t + 4];
                bl[nt][0] = Bl[cb * ROW_W + kb + t];
                bl[nt][1] = Bl[cb * ROW_W + kb + t + 4];
            }
#pragma unroll
            for (int mt = 0; mt < 2; ++mt)
#pragma unroll
                for (int nt = 0; nt < 8; ++nt) {
                    mma16816(acc[mt][nt], ah[mt], bh[nt]);   // hi*hi
                    mma16816(acc[mt][nt], ah[mt], bl[nt]);   // hi*lo
                    mma16816(acc[mt][nt], al[mt], bh[nt]);   // lo*hi
                }
        }

        __syncthreads();
        if (c + STAGES - 1 < NCHUNK) issue_stage((c + STAGES - 1) % STAGES, c + STAGES - 1);
        cp_commit();
    }

    // ---- epilogue: direct coalesced float2 stores ----
    const int b    = j0 >> 11;         // TILE_N divides 2048 -> whole tile one batch
    const int noff = j0 & 2047;
    float* ob = out + ((size_t)b * M_DIM + m0) * N_DIM + noff;
#pragma unroll
    for (int mt = 0; mt < 2; ++mt) {
        const int r0 = warp_m + mt * 16 + g;
#pragma unroll
        for (int nt = 0; nt < 8; ++nt) {
            const int n = warp_n + nt * 8 + 2 * t;
            *reinterpret_cast<float2*>(ob + (size_t)r0 * N_DIM + n) =
                make_float2(acc[mt][nt][0], acc[mt][nt][1]);
            *reinterpret_cast<float2*>(ob + (size_t)(r0 + 8) * N_DIM + n) =
                make_float2(acc[mt][nt][2], acc[mt][nt][3]);
        }
    }
}

// ---------------------------------------------------------------------------
// kernel_launch: zero -> scatter -> convert W -> convert X -> GEMM.
// Graph-capturable, allocation-free.
// Inputs: 0=x f32[B*N*K], 1=values f32[NNZ], 2=row_offsets i32[M+1],
//         3=column_indices i32[NNZ]. Output f32 [B, M, N].
// ---------------------------------------------------------------------------
extern "C" void kernel_launch(void* const* d_in, const int* in_sizes, int n_in,
                              void* d_out, int out_size) {
    const float* x    = (const float*)d_in[0];
    const float* vals = (const float*)d_in[1];
    const int*   roff = (const int*)d_in[2];
    const int*   cidx = (const int*)d_in[3];
    float*       out  = (float*)d_out;

    zero_w<<<(M_DIM * (size_t)K_DIM / 4) / 256, 256>>>();
    scatter_w<<<(NNZ_TOT + 255) / 256, 256>>>(vals, roff, cidx, NNZ_TOT);

    float* gW_ptr;
    cudaGetSymbolAddress((void**)&gW_ptr, g_W);
    uint32_t *whi, *wlo, *xhi, *xlo;
    cudaGetSymbolAddress((void**)&whi, g_Whi);
    cudaGetSymbolAddress((void**)&wlo, g_Wlo);
    cudaGetSymbolAddress((void**)&xhi, g_Xhi);
    cudaGetSymbolAddress((void**)&xlo, g_Xlo);

    conv_split<<<(M_DIM * (size_t)K_DIM / 4) / 256, 256>>>(gW_ptr, whi, wlo);
    conv_split<<<((size_t)NTOT * K_DIM / 4) / 256, 256>>>(x, xhi, xlo);

    static bool attr_done = false;
    if (!attr_done) {
        cudaFuncSetAttribute(spmm_gemm, cudaFuncAttributeMaxDynamicSharedMemorySize, SMEM_BYTES);
        attr_done = true;
    }
    dim3 grid(NTOT / TILE_N, M_DIM / TILE_M, 1);   // (64, 32)
    spmm_gemm<<<grid, 256, SMEM_BYTES>>>(out);
}

// round 10
// speedup vs baseline: 1.6349x; 1.6349x over previous
#include <cuda_runtime.h>
#include <cuda_fp16.h>
#include <cstdint>

// ---------------------------------------------------------------------------
// Problem constants
// ---------------------------------------------------------------------------
#define B_DIM 4
#define N_DIM 2048
#define K_DIM 4096
#define M_DIM 4096
#define NNZ_PER_ROW 409
#define NNZ_TOT (M_DIM * NNZ_PER_ROW)
#define NTOT (B_DIM * N_DIM)            // 8192 GEMM columns

// GEMM tiling
#define TILE_M 128
#define TILE_N 128
#define TILE_K 32
#define NCHUNK (K_DIM / TILE_K)         // 128
#define STAGES 3

// smem: per stage 2 operand tiles (A, B), each 128 rows of 16 kpair-words +
// 4 pad words (stride 20 -> conflict-free for the (g,t) fragment pattern)
#define ROW_W 20
#define OP_WORDS (128 * ROW_W)          // 2560 words
#define STAGE_WORDS (2 * OP_WORDS)      // 5120 words = 20 KB
#define SMEM_BYTES (STAGES * STAGE_WORDS * 4)   // 60 KB

// ---------------------------------------------------------------------------
// Device scratch (sanctioned no-alloc mechanism)
// ---------------------------------------------------------------------------
__device__ float    g_W [(size_t)M_DIM * K_DIM];        // 64 MB dense fp32 W
__device__ uint32_t g_Wh[(size_t)M_DIM * K_DIM / 2];    // fp16 pairs, 32 MB
__device__ uint32_t g_Xh[(size_t)NTOT * K_DIM / 2];     // fp16 pairs, 64 MB

// ---------------------------------------------------------------------------
// Helpers
// ---------------------------------------------------------------------------
__device__ __forceinline__ uint32_t smem_to_u32(const void* p) {
    uint32_t a;
    asm("{ .reg .u64 t; cvta.to.shared.u64 t, %1; cvt.u32.u64 %0, t; }"
        : "=r"(a) : "l"(p));
    return a;
}

__device__ __forceinline__ void cp_async16(uint32_t dst, const void* src) {
    asm volatile("cp.async.cg.shared.global [%0], [%1], 16;"
                 :: "r"(dst), "l"(src) : "memory");
}
__device__ __forceinline__ void cp_commit() {
    asm volatile("cp.async.commit_group;" ::: "memory");
}
template <int N>
__device__ __forceinline__ void cp_wait() {
    asm volatile("cp.async.wait_group %0;" :: "n"(N) : "memory");
}

// mma.sync m16n8k16 fp16 in / fp32 accum (baseline PTX, valid on compute_103)
__device__ __forceinline__ void mma16816(float* c, const uint32_t* a, const uint32_t* b) {
    asm volatile(
        "mma.sync.aligned.m16n8k16.row.col.f32.f16.f16.f32 "
        "{%0,%1,%2,%3}, {%4,%5,%6,%7}, {%8,%9}, {%0,%1,%2,%3};"
        : "+f"(c[0]), "+f"(c[1]), "+f"(c[2]), "+f"(c[3])
        : "r"(a[0]), "r"(a[1]), "r"(a[2]), "r"(a[3]), "r"(b[0]), "r"(b[1]));
}

// ---------------------------------------------------------------------------
// Kernel 1: zero dense W
// ---------------------------------------------------------------------------
__global__ void zero_w() {
    size_t i = (size_t)blockIdx.x * blockDim.x + threadIdx.x;
    reinterpret_cast<float4*>(g_W)[i] = make_float4(0.f, 0.f, 0.f, 0.f);
}

// ---------------------------------------------------------------------------
// Kernel 2: scatter CSR -> dense fp32 W (duplicate cols sum via atomicAdd)
// ---------------------------------------------------------------------------
__global__ void scatter_w(const float* __restrict__ vals,
                          const int* __restrict__ roff,
                          const int* __restrict__ cidx, int nnz) {
    int i = blockIdx.x * blockDim.x + threadIdx.x;
    if (i >= nnz) return;
    int lo = 0, hi = M_DIM;
    while (lo + 1 < hi) {
        int mid = (lo + hi) >> 1;
        if (roff[mid] <= i) lo = mid; else hi = mid;
    }
    atomicAdd(g_W + (size_t)lo * K_DIM + cidx[i], vals[i]);
}

// ---------------------------------------------------------------------------
// Kernel 3/4: fp32 -> fp16x2 conversion
// ---------------------------------------------------------------------------
__global__ void conv_f16(const float* __restrict__ src, uint32_t* __restrict__ dst) {
    size_t i = (size_t)blockIdx.x * blockDim.x + threadIdx.x;
    float4 v = reinterpret_cast<const float4*>(src)[i];
    __half2 h0 = __floats2half2_rn(v.x, v.y);   // .x = low half
    __half2 h1 = __floats2half2_rn(v.z, v.w);
    uint2 o;
    o.x = *reinterpret_cast<uint32_t*>(&h0);
    o.y = *reinterpret_cast<uint32_t*>(&h1);
    reinterpret_cast<uint2*>(dst)[i] = o;
}

// ---------------------------------------------------------------------------
// Kernel 5: fp16 single-pass GEMM via mma.sync.
//   D[m, j] = sum_k W[m,k] * X[j,k]   (A row-major, B col-major: both K-contig)
//   CTA 128x128, 8 warps (4x2), warp 32x64, TILE_K=32, 3-stage cp.async,
//   2 CTAs/SM.
// ---------------------------------------------------------------------------
__global__ void __launch_bounds__(256, 2) spmm_gemm(float* __restrict__ out) {
    extern __shared__ uint32_t sm[];
    const uint32_t smem_base = smem_to_u32(sm);

    const int tid  = threadIdx.x;
    const int wid  = tid >> 5;
    const int lane = tid & 31;
    const int g    = lane >> 2;     // group-of-4 id
    const int t    = lane & 3;

    const int m0 = blockIdx.y * TILE_M;
    const int j0 = blockIdx.x * TILE_N;
    const int warp_m = (wid >> 1) * 32;
    const int warp_n = (wid & 1) * 64;

    float acc[2][8][4];
#pragma unroll
    for (int mt = 0; mt < 2; ++mt)
#pragma unroll
        for (int nt = 0; nt < 8; ++nt)
#pragma unroll
            for (int q = 0; q < 4; ++q) acc[mt][nt][q] = 0.f;

    // ---- stage loader: 1024 x 16B chunks, 4 per thread ----
    auto issue_stage = [&](int stage, int chunk) {
        const int k0 = chunk * TILE_K;
        const uint32_t sbase = smem_base + (uint32_t)stage * STAGE_WORDS * 4;
#pragma unroll
        for (int i = 0; i < 4; ++i) {
            const int cid = tid + i * 256;
            const int seg = cid & 3;
            const int row = (cid >> 2) & 127;
            const int op  = cid >> 9;            // 0=A(W) 1=B(X)
            const int grow = (op == 0) ? (m0 + row) : (j0 + row);
            const size_t pidx = ((size_t)grow * K_DIM + k0 + seg * 8) >> 1;
            const uint32_t* src = (op == 0) ? (g_Wh + pidx) : (g_Xh + pidx);
            const uint32_t dst = sbase + (uint32_t)(op * OP_WORDS + row * ROW_W + seg * 4) * 4;
            cp_async16(dst, src);
        }
    };

    // prologue
    issue_stage(0, 0); cp_commit();
    issue_stage(1, 1); cp_commit();

    for (int c = 0; c < NCHUNK; ++c) {
        cp_wait<1>();
        __syncthreads();

        const uint32_t* A = sm + (c % STAGES) * STAGE_WORDS;
        const uint32_t* Bm = A + OP_WORDS;

#pragma unroll
        for (int ks = 0; ks < 2; ++ks) {
            const int kb = ks * 8;
            uint32_t ah[2][4], bh[8][2];
#pragma unroll
            for (int mt = 0; mt < 2; ++mt) {
                const int rb = warp_m + mt * 16;
                ah[mt][0] = A[(rb + g) * ROW_W + kb + t];
                ah[mt][1] = A[(rb + g + 8) * ROW_W + kb + t];
                ah[mt][2] = A[(rb + g) * ROW_W + kb + t + 4];
                ah[mt][3] = A[(rb + g + 8) * ROW_W + kb + t + 4];
            }
#pragma unroll
            for (int nt = 0; nt < 8; ++nt) {
                const int cb = warp_n + nt * 8 + g;
                bh[nt][0] = Bm[cb * ROW_W + kb + t];
                bh[nt][1] = Bm[cb * ROW_W + kb + t + 4];
            }
#pragma unroll
            for (int mt = 0; mt < 2; ++mt)
#pragma unroll
                for (int nt = 0; nt < 8; ++nt)
                    mma16816(acc[mt][nt], ah[mt], bh[nt]);
        }

        __syncthreads();
        if (c + STAGES - 1 < NCHUNK) issue_stage((c + STAGES - 1) % STAGES, c + STAGES - 1);
        cp_commit();
    }

    // ---- epilogue: direct coalesced float2 stores ----
    const int b    = j0 >> 11;         // TILE_N divides 2048 -> whole tile one batch
    const int noff = j0 & 2047;
    float* ob = out + ((size_t)b * M_DIM + m0) * N_DIM + noff;
#pragma unroll
    for (int mt = 0; mt < 2; ++mt) {
        const int r0 = warp_m + mt * 16 + g;
#pragma unroll
        for (int nt = 0; nt < 8; ++nt) {
            const int n = warp_n + nt * 8 + 2 * t;
            *reinterpret_cast<float2*>(ob + (size_t)r0 * N_DIM + n) =
                make_float2(acc[mt][nt][0], acc[mt][nt][1]);
            *reinterpret_cast<float2*>(ob + (size_t)(r0 + 8) * N_DIM + n) =
                make_float2(acc[mt][nt][2], acc[mt][nt][3]);
        }
    }
}

// ---------------------------------------------------------------------------
// kernel_launch: zero -> scatter -> convert W -> convert X -> GEMM.
// Graph-capturable, allocation-free.
// Inputs: 0=x f32[B*N*K], 1=values f32[NNZ], 2=row_offsets i32[M+1],
//         3=column_indices i32[NNZ]. Output f32 [B, M, N].
// ---------------------------------------------------------------------------
extern "C" void kernel_launch(void* const* d_in, const int* in_sizes, int n_in,
                              void* d_out, int out_size) {
    const float* x    = (const float*)d_in[0];
    const float* vals = (const float*)d_in[1];
    const int*   roff = (const int*)d_in[2];
    const int*   cidx = (const int*)d_in[3];
    float*       out  = (float*)d_out;

    zero_w<<<(M_DIM * (size_t)K_DIM / 4) / 256, 256>>>();
    scatter_w<<<(NNZ_TOT + 255) / 256, 256>>>(vals, roff, cidx, NNZ_TOT);

    float* gW_ptr;
    cudaGetSymbolAddress((void**)&gW_ptr, g_W);
    uint32_t *wh, *xh;
    cudaGetSymbolAddress((void**)&wh, g_Wh);
    cudaGetSymbolAddress((void**)&xh, g_Xh);

    conv_f16<<<(M_DIM * (size_t)K_DIM / 4) / 256, 256>>>(gW_ptr, wh);
    conv_f16<<<((size_t)NTOT * K_DIM / 4) / 256, 256>>>(x, xh);

    cudaFuncSetAttribute(spmm_gemm, cudaFuncAttributeMaxDynamicSharedMemorySize, SMEM_BYTES);
    dim3 grid(NTOT / TILE_N, M_DIM / TILE_M, 1);   // (64, 32)
    spmm_gemm<<<grid, 256, SMEM_BYTES>>>(out);
}

// round 14
// speedup vs baseline: 3.1448x; 1.9236x over previous
#include <cuda_runtime.h>
#include <cuda_fp16.h>
#include <cstdint>

// ---------------------------------------------------------------------------
// Problem constants
// ---------------------------------------------------------------------------
#define B_DIM 4
#define N_DIM 2048
#define K_DIM 4096
#define M_DIM 4096
#define NNZ_PER_ROW 409
#define NNZ_TOT (M_DIM * NNZ_PER_ROW)
#define NTOT (B_DIM * N_DIM)            // 8192 GEMM columns

// GEMM tiling
#define TILE_M 128
#define TILE_N 128
#define TILE_K 64
#define NCHUNK (K_DIM / TILE_K)         // 64
#define STAGES 2

// smem: per stage 2 operand tiles (A, B), each 128 rows of 32 kpair-words +
// 4 pad words (stride 36 -> conflict-free for LDSM phases: r*36 mod 32 = 4r)
#define ROW_W 36
#define OP_WORDS (128 * ROW_W)          // 4608 words
#define STAGE_WORDS (2 * OP_WORDS)      // 9216 words = 36 KB
#define STAGE_BYTES (STAGE_WORDS * 4)
#define SMEM_BYTES (STAGES * STAGE_BYTES)   // 72 KB

// ---------------------------------------------------------------------------
// Device scratch (sanctioned no-alloc mechanism)
// ---------------------------------------------------------------------------
__device__ float    g_W [(size_t)M_DIM * K_DIM];        // 64 MB dense fp32 W
__device__ uint32_t g_Wh[(size_t)M_DIM * K_DIM / 2];    // fp16 pairs, 32 MB
__device__ uint32_t g_Xh[(size_t)NTOT * K_DIM / 2];     // fp16 pairs, 64 MB

// ---------------------------------------------------------------------------
// Helpers
// ---------------------------------------------------------------------------
__device__ __forceinline__ uint32_t smem_to_u32(const void* p) {
    uint32_t a;
    asm("{ .reg .u64 t; cvta.to.shared.u64 t, %1; cvt.u32.u64 %0, t; }"
        : "=r"(a) : "l"(p));
    return a;
}

__device__ __forceinline__ void cp_async16(uint32_t dst, const void* src) {
    asm volatile("cp.async.cg.shared.global [%0], [%1], 16;"
                 :: "r"(dst), "l"(src) : "memory");
}
__device__ __forceinline__ void cp_commit() {
    asm volatile("cp.async.commit_group;" ::: "memory");
}
template <int N>
__device__ __forceinline__ void cp_wait() {
    asm volatile("cp.async.wait_group %0;" :: "n"(N) : "memory");
}

__device__ __forceinline__ void ldsm_x4(uint32_t* r, uint32_t addr) {
    asm volatile("ldmatrix.sync.aligned.m8n8.x4.shared.b16 {%0,%1,%2,%3}, [%4];"
                 : "=r"(r[0]), "=r"(r[1]), "=r"(r[2]), "=r"(r[3]) : "r"(addr));
}

// mma.sync m16n8k16 fp16 in / fp32 accum (baseline PTX, valid on compute_103)
__device__ __forceinline__ void mma16816(float* c, const uint32_t* a,
                                         uint32_t b0, uint32_t b1) {
    asm volatile(
        "mma.sync.aligned.m16n8k16.row.col.f32.f16.f16.f32 "
        "{%0,%1,%2,%3}, {%4,%5,%6,%7}, {%8,%9}, {%0,%1,%2,%3};"
        : "+f"(c[0]), "+f"(c[1]), "+f"(c[2]), "+f"(c[3])
        : "r"(a[0]), "r"(a[1]), "r"(a[2]), "r"(a[3]), "r"(b0), "r"(b1));
}

// ---------------------------------------------------------------------------
// Kernel 1: zero dense W
// ---------------------------------------------------------------------------
__global__ void zero_w() {
    size_t i = (size_t)blockIdx.x * blockDim.x + threadIdx.x;
    reinterpret_cast<float4*>(g_W)[i] = make_float4(0.f, 0.f, 0.f, 0.f);
}

// ---------------------------------------------------------------------------
// Kernel 2: scatter CSR -> dense fp32 W (duplicate cols sum via atomicAdd)
// ---------------------------------------------------------------------------
__global__ void scatter_w(const float* __restrict__ vals,
                          const int* __restrict__ roff,
                          const int* __restrict__ cidx, int nnz) {
    int i = blockIdx.x * blockDim.x + threadIdx.x;
    if (i >= nnz) return;
    int lo = 0, hi = M_DIM;
    while (lo + 1 < hi) {
        int mid = (lo + hi) >> 1;
        if (roff[mid] <= i) lo = mid; else hi = mid;
    }
    atomicAdd(g_W + (size_t)lo * K_DIM + cidx[i], vals[i]);
}

// ---------------------------------------------------------------------------
// Kernel 3/4: fp32 -> fp16x2 conversion
// ---------------------------------------------------------------------------
__global__ void conv_f16(const float* __restrict__ src, uint32_t* __restrict__ dst) {
    size_t i = (size_t)blockIdx.x * blockDim.x + threadIdx.x;
    float4 v = reinterpret_cast<const float4*>(src)[i];
    __half2 h0 = __floats2half2_rn(v.x, v.y);
    __half2 h1 = __floats2half2_rn(v.z, v.w);
    uint2 o;
    o.x = *reinterpret_cast<uint32_t*>(&h0);
    o.y = *reinterpret_cast<uint32_t*>(&h1);
    reinterpret_cast<uint2*>(dst)[i] = o;
}

// ---------------------------------------------------------------------------
// Kernel 5: fp16 GEMM via mma.sync + ldmatrix.
//   D[m, j] = sum_k W[m,k] * X[j,k]   (A row-major, B col-major: both K-contig)
//   CTA 128x128, 8 warps (4x2), warp 32x64, TILE_K=64, 2-stage cp.async,
//   2 CTAs/SM.
// ---------------------------------------------------------------------------
__global__ void __launch_bounds__(256, 2) spmm_gemm(float* __restrict__ out) {
    extern __shared__ uint32_t sm[];
    const uint32_t smem_base = smem_to_u32(sm);

    const int tid  = threadIdx.x;
    const int wid  = tid >> 5;
    const int lane = tid & 31;
    const int g    = lane >> 2;
    const int t    = lane & 3;

    const int m0 = blockIdx.y * TILE_M;
    const int j0 = blockIdx.x * TILE_N;
    const int warp_m = (wid >> 1) * 32;
    const int warp_n = (wid & 1) * 64;

    float acc[2][8][4];
#pragma unroll
    for (int mt = 0; mt < 2; ++mt)
#pragma unroll
        for (int nt = 0; nt < 8; ++nt)
#pragma unroll
            for (int q = 0; q < 4; ++q) acc[mt][nt][q] = 0.f;

    // ---- ldmatrix per-lane base addresses (byte offsets inside a stage) ----
    // A tile (op 0): x4 mats = (m0-7,k0-7),(m8-15,k0-7),(m0-7,k8-15),(m8-15,k8-15)
    const int lrow   = lane & 15;
    const int khalfA = lane >> 4;
    uint32_t a_off[2];
#pragma unroll
    for (int mt = 0; mt < 2; ++mt)
        a_off[mt] = (uint32_t)(((warp_m + mt * 16 + lrow) * ROW_W + khalfA * 4) * 4);
    // B tile (op 1): x4 mats = b0(nt=2p), b1(nt=2p), b0(nt=2p+1), b1(nt=2p+1)
    const int nrow_l = (lane & 7) + ((lane >> 4) & 1) * 8;
    const int khalfB = (lane >> 3) & 1;
    uint32_t b_off[4];
#pragma unroll
    for (int p = 0; p < 4; ++p)
        b_off[p] = (uint32_t)((OP_WORDS + (warp_n + p * 16 + nrow_l) * ROW_W + khalfB * 4) * 4);

    // ---- stage loader: 2048 x 16B chunks per stage, 8 per thread ----
    auto issue_stage = [&](int stage, int chunk) {
        const int k0 = chunk * TILE_K;
        const uint32_t sbase = smem_base + (uint32_t)stage * STAGE_BYTES;
#pragma unroll
        for (int i = 0; i < 8; ++i) {
            const int cid = tid + i * 256;
            const int seg = cid & 7;
            const int row = (cid >> 3) & 127;
            const int op  = cid >> 10;           // 0=A(W) 1=B(X)
            const int grow = (op == 0) ? (m0 + row) : (j0 + row);
            const size_t pidx = ((size_t)grow * K_DIM + k0) / 2 + seg * 4;
            const uint32_t* src = (op == 0) ? (g_Wh + pidx) : (g_Xh + pidx);
            const uint32_t dst = sbase + (uint32_t)(op * OP_WORDS + row * ROW_W + seg * 4) * 4;
            cp_async16(dst, src);
        }
    };

    // prologue
    issue_stage(0, 0); cp_commit();
    issue_stage(1, 1); cp_commit();

    for (int c = 0; c < NCHUNK; ++c) {
        cp_wait<1>();
        __syncthreads();

        const uint32_t sb = smem_base + (uint32_t)(c & 1) * STAGE_BYTES;

#pragma unroll
        for (int ks = 0; ks < 4; ++ks) {
            const uint32_t ko = (uint32_t)(ks * 32);   // 8 words = 32 bytes per k16
            uint32_t a[2][4], b[4][4];
#pragma unroll
            for (int mt = 0; mt < 2; ++mt) ldsm_x4(a[mt], sb + a_off[mt] + ko);
#pragma unroll
            for (int p = 0; p < 4; ++p)    ldsm_x4(b[p], sb + b_off[p] + ko);
#pragma unroll
            for (int mt = 0; mt < 2; ++mt)
#pragma unroll
                for (int p = 0; p < 4; ++p) {
                    mma16816(acc[mt][2 * p],     a[mt], b[p][0], b[p][1]);
                    mma16816(acc[mt][2 * p + 1], a[mt], b[p][2], b[p][3]);
                }
        }

        __syncthreads();
        if (c + 2 < NCHUNK) issue_stage(c & 1, c + 2);
        cp_commit();
    }

    // ---- epilogue: direct coalesced float2 stores ----
    const int b    = j0 >> 11;         // TILE_N divides 2048 -> tile in one batch
    const int noff = j0 & 2047;
    float* ob = out + ((size_t)b * M_DIM + m0) * N_DIM + noff;
#pragma unroll
    for (int mt = 0; mt < 2; ++mt) {
        const int r0 = warp_m + mt * 16 + g;
#pragma unroll
        for (int nt = 0; nt < 8; ++nt) {
            const int n = warp_n + nt * 8 + 2 * t;
            *reinterpret_cast<float2*>(ob + (size_t)r0 * N_DIM + n) =
                make_float2(acc[mt][nt][0], acc[mt][nt][1]);
            *reinterpret_cast<float2*>(ob + (size_t)(r0 + 8) * N_DIM + n) =
                make_float2(acc[mt][nt][2], acc[mt][nt][3]);
        }
    }
}

// ---------------------------------------------------------------------------
// kernel_launch: zero -> scatter -> convert W -> convert X -> GEMM.
// Graph-capturable, allocation-free.
// Inputs: 0=x f32[B*N*K], 1=values f32[NNZ], 2=row_offsets i32[M+1],
//         3=column_indices i32[NNZ]. Output f32 [B, M, N].
// ---------------------------------------------------------------------------
extern "C" void kernel_launch(void* const* d_in, const int* in_sizes, int n_in,
                              void* d_out, int out_size) {
    const float* x    = (const float*)d_in[0];
    const float* vals = (const float*)d_in[1];
    const int*   roff = (const int*)d_in[2];
    const int*   cidx = (const int*)d_in[3];
    float*       out  = (float*)d_out;

    zero_w<<<(M_DIM * (size_t)K_DIM / 4) / 256, 256>>>();
    scatter_w<<<(NNZ_TOT + 255) / 256, 256>>>(vals, roff, cidx, NNZ_TOT);

    float* gW_ptr;
    cudaGetSymbolAddress((void**)&gW_ptr, g_W);
    uint32_t *wh, *xh;
    cudaGetSymbolAddress((void**)&wh, g_Wh);
    cudaGetSymbolAddress((void**)&xh, g_Xh);

    conv_f16<<<(M_DIM * (size_t)K_DIM / 4) / 256, 256>>>(gW_ptr, wh);
    conv_f16<<<((size_t)NTOT * K_DIM / 4) / 256, 256>>>(x, xh);

    cudaFuncSetAttribute(spmm_gemm, cudaFuncAttributeMaxDynamicSharedMemorySize, SMEM_BYTES);
    dim3 grid(NTOT / TILE_N, M_DIM / TILE_M, 1);   // (64, 32)
    spmm_gemm<<<grid, 256, SMEM_BYTES>>>(out);
}

// round 16
// speedup vs baseline: 3.2086x; 1.0203x over previous
#include <cuda_runtime.h>
#include <cuda_fp16.h>
#include <cstdint>

// ---------------------------------------------------------------------------
// Problem constants
// ---------------------------------------------------------------------------
#define B_DIM 4
#define N_DIM 2048
#define K_DIM 4096
#define M_DIM 4096
#define NNZ_PER_ROW 409
#define NNZ_TOT (M_DIM * NNZ_PER_ROW)
#define NTOT (B_DIM * N_DIM)            // 8192 GEMM columns

// GEMM tiling
#define TILE_M 128
#define TILE_N 128
#define TILE_K 64
#define NCHUNK (K_DIM / TILE_K)         // 64
#define STAGES 2

// smem: per stage 2 operand tiles (A, B), each 128 rows of 32 kpair-words +
// 4 pad words (stride 36 -> conflict-free for LDSM phases: r*36 mod 32 = 4r)
#define ROW_W 36
#define OP_WORDS (128 * ROW_W)          // 4608 words
#define STAGE_WORDS (2 * OP_WORDS)      // 9216 words = 36 KB
#define STAGE_BYTES (STAGE_WORDS * 4)
#define SMEM_BYTES (STAGES * STAGE_BYTES)   // 72 KB

// ---------------------------------------------------------------------------
// Device scratch (sanctioned no-alloc mechanism)
// ---------------------------------------------------------------------------
__device__ uint32_t g_Wh[(size_t)M_DIM * K_DIM / 2];    // fp16 pairs, 32 MB
__device__ uint32_t g_Xh[(size_t)NTOT * K_DIM / 2];     // fp16 pairs, 64 MB

// ---------------------------------------------------------------------------
// Helpers
// ---------------------------------------------------------------------------
__device__ __forceinline__ uint32_t smem_to_u32(const void* p) {
    uint32_t a;
    asm("{ .reg .u64 t; cvta.to.shared.u64 t, %1; cvt.u32.u64 %0, t; }"
        : "=r"(a) : "l"(p));
    return a;
}

__device__ __forceinline__ void cp_async16(uint32_t dst, const void* src) {
    asm volatile("cp.async.cg.shared.global [%0], [%1], 16;"
                 :: "r"(dst), "l"(src) : "memory");
}
__device__ __forceinline__ void cp_commit() {
    asm volatile("cp.async.commit_group;" ::: "memory");
}
template <int N>
__device__ __forceinline__ void cp_wait() {
    asm volatile("cp.async.wait_group %0;" :: "n"(N) : "memory");
}

__device__ __forceinline__ void ldsm_x4(uint32_t* r, uint32_t addr) {
    asm volatile("ldmatrix.sync.aligned.m8n8.x4.shared.b16 {%0,%1,%2,%3}, [%4];"
                 : "=r"(r[0]), "=r"(r[1]), "=r"(r[2]), "=r"(r[3]) : "r"(addr));
}

// mma.sync m16n8k16 fp16 in / fp32 accum (baseline PTX, valid on compute_103)
__device__ __forceinline__ void mma16816(float* c, const uint32_t* a,
                                         uint32_t b0, uint32_t b1) {
    asm volatile(
        "mma.sync.aligned.m16n8k16.row.col.f32.f16.f16.f32 "
        "{%0,%1,%2,%3}, {%4,%5,%6,%7}, {%8,%9}, {%0,%1,%2,%3};"
        : "+f"(c[0]), "+f"(c[1]), "+f"(c[2]), "+f"(c[3])
        : "r"(a[0]), "r"(a[1]), "r"(a[2]), "r"(a[3]), "r"(b0), "r"(b1));
}

// ---------------------------------------------------------------------------
// Kernel 1: zero fp16 W
// ---------------------------------------------------------------------------
__global__ void zero_wh() {
    size_t i = (size_t)blockIdx.x * blockDim.x + threadIdx.x;
    reinterpret_cast<uint4*>(g_Wh)[i] = make_uint4(0, 0, 0, 0);
}

// ---------------------------------------------------------------------------
// Kernel 2: scatter CSR -> dense fp16 W directly (native f16 red; duplicate
// cols sum in fp16 — same rounding scale as the convert path)
// ---------------------------------------------------------------------------
__global__ void scatter_w(const float* __restrict__ vals,
                          const int* __restrict__ roff,
                          const int* __restrict__ cidx, int nnz) {
    int i = blockIdx.x * blockDim.x + threadIdx.x;
    if (i >= nnz) return;
    int lo = 0, hi = M_DIM;
    while (lo + 1 < hi) {
        int mid = (lo + hi) >> 1;
        if (roff[mid] <= i) lo = mid; else hi = mid;
    }
    __half* wh = reinterpret_cast<__half*>(g_Wh);
    atomicAdd(wh + (size_t)lo * K_DIM + cidx[i], __float2half(vals[i]));
}

// ---------------------------------------------------------------------------
// Kernel 3: fp32 -> fp16x2 conversion (X)
// ---------------------------------------------------------------------------
__global__ void conv_f16(const float* __restrict__ src, uint32_t* __restrict__ dst) {
    size_t i = (size_t)blockIdx.x * blockDim.x + threadIdx.x;
    float4 v = reinterpret_cast<const float4*>(src)[i];
    __half2 h0 = __floats2half2_rn(v.x, v.y);
    __half2 h1 = __floats2half2_rn(v.z, v.w);
    uint2 o;
    o.x = *reinterpret_cast<uint32_t*>(&h0);
    o.y = *reinterpret_cast<uint32_t*>(&h1);
    reinterpret_cast<uint2*>(dst)[i] = o;
}

// ---------------------------------------------------------------------------
// Kernel 4: fp16 GEMM via mma.sync + ldmatrix.
//   D[m, j] = sum_k W[m,k] * X[j,k]   (A row-major, B col-major: both K-contig)
//   CTA 128x128, 4 warps (2x2), warp 64x64, TILE_K=64, 2-stage cp.async,
//   2 CTAs/SM. 2x2 warp layout minimizes cross-warp fragment re-reads
//   (64 KB LDSM reads per 36 KB stage vs 96 KB with 8 warps).
// ---------------------------------------------------------------------------
__global__ void __launch_bounds__(128, 2) spmm_gemm(float* __restrict__ out) {
    extern __shared__ uint32_t sm[];
    const uint32_t smem_base = smem_to_u32(sm);

    const int tid  = threadIdx.x;
    const int wid  = tid >> 5;
    const int lane = tid & 31;
    const int g    = lane >> 2;
    const int t    = lane & 3;

    const int m0 = blockIdx.y * TILE_M;
    const int j0 = blockIdx.x * TILE_N;
    const int warp_m = (wid >> 1) * 64;
    const int warp_n = (wid & 1) * 64;

    float acc[4][8][4];
#pragma unroll
    for (int mt = 0; mt < 4; ++mt)
#pragma unroll
        for (int nt = 0; nt < 8; ++nt)
#pragma unroll
            for (int q = 0; q < 4; ++q) acc[mt][nt][q] = 0.f;

    // ---- ldmatrix per-lane base addresses (byte offsets inside a stage) ----
    // A (op 0): x4 mats = (m0-7,k0-7),(m8-15,k0-7),(m0-7,k8-15),(m8-15,k8-15)
    const int lrow   = lane & 15;
    const int khalfA = lane >> 4;
    uint32_t a_off[4];
#pragma unroll
    for (int mt = 0; mt < 4; ++mt)
        a_off[mt] = (uint32_t)(((warp_m + mt * 16 + lrow) * ROW_W + khalfA * 4) * 4);
    // B (op 1): x4 mats = b0(nt=2p), b1(nt=2p), b0(nt=2p+1), b1(nt=2p+1)
    const int nrow_l = (lane & 7) + ((lane >> 4) & 1) * 8;
    const int khalfB = (lane >> 3) & 1;
    uint32_t b_off[4];
#pragma unroll
    for (int p = 0; p < 4; ++p)
        b_off[p] = (uint32_t)((OP_WORDS + (warp_n + p * 16 + nrow_l) * ROW_W + khalfB * 4) * 4);

    // ---- stage loader: 2048 x 16B chunks per stage, 16 per thread ----
    auto issue_stage = [&](int stage, int chunk) {
        const int k0 = chunk * TILE_K;
        const uint32_t sbase = smem_base + (uint32_t)stage * STAGE_BYTES;
#pragma unroll
        for (int i = 0; i < 16; ++i) {
            const int cid = tid + i * 128;
            const int seg = cid & 7;
            const int row = (cid >> 3) & 127;
            const int op  = cid >> 10;           // 0=A(W) 1=B(X)
            const int grow = (op == 0) ? (m0 + row) : (j0 + row);
            const size_t pidx = ((size_t)grow * K_DIM + k0) / 2 + seg * 4;
            const uint32_t* src = (op == 0) ? (g_Wh + pidx) : (g_Xh + pidx);
            const uint32_t dst = sbase + (uint32_t)(op * OP_WORDS + row * ROW_W + seg * 4) * 4;
            cp_async16(dst, src);
        }
    };

    // prologue
    issue_stage(0, 0); cp_commit();
    issue_stage(1, 1); cp_commit();

    for (int c = 0; c < NCHUNK; ++c) {
        cp_wait<1>();
        __syncthreads();

        const uint32_t sb = smem_base + (uint32_t)(c & 1) * STAGE_BYTES;

#pragma unroll
        for (int ks = 0; ks < 4; ++ks) {
            const uint32_t ko = (uint32_t)(ks * 32);   // 8 words = 32B per k16
            uint32_t a[4][4], b[4][4];
#pragma unroll
            for (int mt = 0; mt < 4; ++mt) ldsm_x4(a[mt], sb + a_off[mt] + ko);
#pragma unroll
            for (int p = 0; p < 4; ++p)    ldsm_x4(b[p], sb + b_off[p] + ko);
#pragma unroll
            for (int mt = 0; mt < 4; ++mt)
#pragma unroll
                for (int p = 0; p < 4; ++p) {
                    mma16816(acc[mt][2 * p],     a[mt], b[p][0], b[p][1]);
                    mma16816(acc[mt][2 * p + 1], a[mt], b[p][2], b[p][3]);
                }
        }

        __syncthreads();
        if (c + 2 < NCHUNK) issue_stage(c & 1, c + 2);
        cp_commit();
    }

    // ---- epilogue: direct coalesced float2 stores ----
    const int b    = j0 >> 11;         // TILE_N divides 2048 -> tile in one batch
    const int noff = j0 & 2047;
    float* ob = out + ((size_t)b * M_DIM + m0) * N_DIM + noff;
#pragma unroll
    for (int mt = 0; mt < 4; ++mt) {
        const int r0 = warp_m + mt * 16 + g;
#pragma unroll
        for (int nt = 0; nt < 8; ++nt) {
            const int n = warp_n + nt * 8 + 2 * t;
            *reinterpret_cast<float2*>(ob + (size_t)r0 * N_DIM + n) =
                make_float2(acc[mt][nt][0], acc[mt][nt][1]);
            *reinterpret_cast<float2*>(ob + (size_t)(r0 + 8) * N_DIM + n) =
                make_float2(acc[mt][nt][2], acc[mt][nt][3]);
        }
    }
}

// ---------------------------------------------------------------------------
// kernel_launch: zero fp16 W -> scatter(fp16) -> convert X -> GEMM.
// Graph-capturable, allocation-free.
// Inputs: 0=x f32[B*N*K], 1=values f32[NNZ], 2=row_offsets i32[M+1],
//         3=column_indices i32[NNZ]. Output f32 [B, M, N].
// ---------------------------------------------------------------------------
extern "C" void kernel_launch(void* const* d_in, const int* in_sizes, int n_in,
                              void* d_out, int out_size) {
    const float* x    = (const float*)d_in[0];
    const float* vals = (const float*)d_in[1];
    const int*   roff = (const int*)d_in[2];
    const int*   cidx = (const int*)d_in[3];
    float*       out  = (float*)d_out;

    zero_wh<<<((size_t)M_DIM * K_DIM / 8) / 256, 256>>>();
    scatter_w<<<(NNZ_TOT + 255) / 256, 256>>>(vals, roff, cidx, NNZ_TOT);

    uint32_t* xh;
    cudaGetSymbolAddress((void**)&xh, g_Xh);
    conv_f16<<<((size_t)NTOT * K_DIM / 4) / 256, 256>>>(x, xh);

    cudaFuncSetAttribute(spmm_gemm, cudaFuncAttributeMaxDynamicSharedMemorySize, SMEM_BYTES);
    dim3 grid(NTOT / TILE_N, M_DIM / TILE_M, 1);   // (64, 32)
    spmm_gemm<<<grid, 128, SMEM_BYTES>>>(out);
}